// round 2
// baseline (speedup 1.0000x reference)
#include <cuda_runtime.h>

#define BB 4
#define CC 256
#define HH 64
#define WW 64
#define HW 4096
#define KK 9
#define OCO 18   // offset conv out channels
#define OO 256   // deform conv out channels
#define GEPS 1e-5f

// ---------------- scratch (device globals; no allocations) ----------------
__device__ float g_xt[BB * HW * CC];      // x in NHWC           16.8 MB
__device__ float g_off[BB * HW * OCO];    // offsets NHWC         1.2 MB
__device__ float g_wo[KK * CC * OCO];     // offset w  [k][c][oc]
__device__ float g_wd[KK * CC * OO];      // deform w  [k][c][o]  2.36 MB
__device__ float g_y[BB * HW * OO];       // pre-GN out NHWC     16.8 MB
__device__ float g_gn[BB * 32 * 2];       // per-(b,group) mean, rstd

// ---------------- K0: x NCHW -> NHWC ----------------
__global__ void k_xt(const float* __restrict__ x) {
    __shared__ float sm[32][65];
    int tid = threadIdx.x;
    int b = blockIdx.z, h = blockIdx.y, c0 = blockIdx.x * 32;
    // read: 32 c x 64 w tile, coalesced along w
    for (int i = tid; i < 2048; i += 256) {
        int w = i & 63, c = i >> 6;
        sm[c][w] = x[((b * CC + c0 + c) * HH + h) * WW + w];
    }
    __syncthreads();
    // write coalesced along c
    for (int i = tid; i < 2048; i += 256) {
        int c = i & 31, w = i >> 5;
        g_xt[((b * HW + h * WW + w) << 8) + c0 + c] = sm[c][w];
    }
}

// ---------------- K0b: weight transposes ----------------
__global__ void k_wd(const float* __restrict__ dw) {
    int idx = blockIdx.x * blockDim.x + threadIdx.x;
    if (idx >= KK * CC * OO) return;
    int o = idx & 255;
    int t = idx >> 8;
    int c = t & 255;
    int k = t >> 8;
    g_wd[idx] = dw[(o * CC + c) * KK + k];
}
__global__ void k_wo(const float* __restrict__ ow) {
    int idx = blockIdx.x * blockDim.x + threadIdx.x;
    if (idx >= KK * CC * OCO) return;
    int oc = idx % OCO;
    int t = idx / OCO;
    int c = t & 255;
    int k = t >> 8;
    g_wo[idx] = ow[(oc * CC + c) * KK + k];
}

// ---------------- K1: offset conv (dense 3x3, 256->18, +bias) ----------------
// CTA: (ypair, b), 128 threads = 128 pixels (2 rows)
__global__ void __launch_bounds__(128) k_offconv(const float* __restrict__ obias) {
    __shared__ float s[128][65];
    __shared__ float wo_s[64 * OCO];
    int tid = threadIdx.x;
    int b = blockIdx.y, y0r = blockIdx.x * 2;
    int yloc = tid >> 6, xcol = tid & 63;
    int y = y0r + yloc;
    int lane = tid & 31, wrp = tid >> 5;
    float acc[OCO];
#pragma unroll
    for (int i = 0; i < OCO; i++) acc[i] = 0.f;

    for (int k = 0; k < KK; k++) {
        int ky = k / 3, kx = k % 3;
        for (int ch = 0; ch < 4; ch++) {
            int c0 = ch * 64;
            // stage weights [64 c][18 oc]
            for (int i = tid; i < 64 * OCO; i += 128)
                wo_s[i] = g_wo[(k * CC + c0) * OCO + i];
            // stage x samples: each warp loads its 32 pixels, 64 channels
            for (int pp = 0; pp < 32; pp++) {
                int p2 = wrp * 32 + pp;
                int yy = y0r + (p2 >> 6) + ky - 1;
                int xx = (p2 & 63) + kx - 1;
                bool v = ((unsigned)yy < 64u) && ((unsigned)xx < 64u);
                int yc = v ? yy : 0, xc = v ? xx : 0;
                const float* src = g_xt + (((b * HH + yc) * WW + xc) << 8) + c0;
                s[p2][lane]      = v ? src[lane]      : 0.f;
                s[p2][lane + 32] = v ? src[lane + 32] : 0.f;
            }
            __syncthreads();
            for (int cc = 0; cc < 64; cc++) {
                float xv = s[tid][cc];
                const float* wp = &wo_s[cc * OCO];
#pragma unroll
                for (int oc = 0; oc < OCO; oc++) acc[oc] = fmaf(xv, wp[oc], acc[oc]);
            }
            __syncthreads();
        }
    }
    float* op = g_off + ((b * HW) + y * WW + xcol) * OCO;
#pragma unroll
    for (int oc = 0; oc < OCO; oc++) op[oc] = acc[oc] + obias[oc];
}

// ---------------- K2: deformable sample + GEMM ----------------
// CTA: (y, b), 256 threads. Tile: 64 pixels (one row) x 256 outputs.
// Thread tile: 8 outputs x 8 pixels.
__global__ void __launch_bounds__(256, 2) k_deform() {
    extern __shared__ float sh[];
    float* s = sh;                      // [64][256]
    float* pw = sh + 16384;             // [4][64] bilinear weights
    int* pidx = (int*)(sh + 16640);     // [4][64] corner row bases

    int tid = threadIdx.x;
    int b = blockIdx.y, y = blockIdx.x;
    int o0 = (tid & 31) << 3;
    int p0 = (tid >> 5) << 3;

    float acc[64];
#pragma unroll
    for (int i = 0; i < 64; i++) acc[i] = 0.f;

    for (int k = 0; k < KK; k++) {
        int ky = k / 3, kx = k % 3;
        if (tid < 64) {
            int p = tid;
            const float* ob = g_off + ((b * HW) + (y << 6) + p) * OCO + (k << 1);
            float dy = ob[0], dx = ob[1];
            float py = (float)(y + ky - 1) + dy;
            float px = (float)(p + kx - 1) + dx;
            float yf = floorf(py), xf = floorf(px);
            float ty = py - yf, tx = px - xf;
            int iy = (int)yf, ix = (int)xf;
#pragma unroll
            for (int ci = 0; ci < 4; ci++) {
                int yy = iy + (ci >> 1), xx = ix + (ci & 1);
                float wy = (ci >> 1) ? ty : 1.f - ty;
                float wx = (ci & 1) ? tx : 1.f - tx;
                bool v = ((unsigned)yy < 64u) && ((unsigned)xx < 64u);
                int yc = v ? yy : 0, xc = v ? xx : 0;
                pw[ci * 64 + p] = v ? wy * wx : 0.f;
                pidx[ci * 64 + p] = (((b * HH + yc) << 6) + xc) << 8;
            }
        }
        __syncthreads();
        // cooperative bilinear sample into s[p][c], c = tid (coalesced)
        {
            int c = tid;
#pragma unroll 4
            for (int p = 0; p < 64; p++) {
                float v = pw[p] * g_xt[pidx[p] + c];
                v = fmaf(pw[64 + p],  g_xt[pidx[64 + p] + c],  v);
                v = fmaf(pw[128 + p], g_xt[pidx[128 + p] + c], v);
                v = fmaf(pw[192 + p], g_xt[pidx[192 + p] + c], v);
                s[(p << 8) + c] = v;
            }
        }
        __syncthreads();
        // GEMM accumulate over this tap's 256 channels
        const float* wk = g_wd + (k << 16);
#pragma unroll 2
        for (int c = 0; c < 256; c++) {
            const float* wr = wk + (c << 8) + o0;
            float4 wa = *(const float4*)wr;
            float4 wb = *(const float4*)(wr + 4);
#pragma unroll
            for (int jp = 0; jp < 8; jp++) {
                float sv = s[((p0 + jp) << 8) + c];
                float* a = acc + jp * 8;
                a[0] = fmaf(sv, wa.x, a[0]);
                a[1] = fmaf(sv, wa.y, a[1]);
                a[2] = fmaf(sv, wa.z, a[2]);
                a[3] = fmaf(sv, wa.w, a[3]);
                a[4] = fmaf(sv, wb.x, a[4]);
                a[5] = fmaf(sv, wb.y, a[5]);
                a[6] = fmaf(sv, wb.z, a[6]);
                a[7] = fmaf(sv, wb.w, a[7]);
            }
        }
        __syncthreads();
    }
    // epilogue: NHWC store
#pragma unroll
    for (int jp = 0; jp < 8; jp++) {
        int p = p0 + jp;
        float* op = g_y + (((b * HW) + (y << 6) + p) << 8) + o0;
        float4 v0 = make_float4(acc[jp * 8 + 0], acc[jp * 8 + 1], acc[jp * 8 + 2], acc[jp * 8 + 3]);
        float4 v1 = make_float4(acc[jp * 8 + 4], acc[jp * 8 + 5], acc[jp * 8 + 6], acc[jp * 8 + 7]);
        *(float4*)op = v0;
        *(float4*)(op + 4) = v1;
    }
}

// ---------------- K3: GroupNorm statistics ----------------
__global__ void __launch_bounds__(1024) k_gnred() {
    int b = blockIdx.x, tid = threadIdx.x;
    int o = tid & 255, pq = tid >> 8;
    const float* base = g_y + ((size_t)b * HW * OO);
    float sm = 0.f, sq = 0.f;
    for (int p = pq; p < HW; p += 4) {
        float v = base[(p << 8) + o];
        sm += v;
        sq = fmaf(v, v, sq);
    }
    __shared__ float rs[1024], rq[1024];
    rs[tid] = sm; rq[tid] = sq;
    __syncthreads();
    if (tid < 256) {
        rs[tid] += rs[tid + 256] + rs[tid + 512] + rs[tid + 768];
        rq[tid] += rq[tid + 256] + rq[tid + 512] + rq[tid + 768];
    }
    __syncthreads();
    if (tid < 32) {
        float S = 0.f, Q = 0.f;
#pragma unroll
        for (int j = 0; j < 8; j++) { S += rs[tid * 8 + j]; Q += rq[tid * 8 + j]; }
        const float inv = 1.f / (8.f * HW);
        float mean = S * inv;
        float var = Q * inv - mean * mean;
        g_gn[(b * 32 + tid) * 2] = mean;
        g_gn[(b * 32 + tid) * 2 + 1] = rsqrtf(var + GEPS);
    }
}

// ---------------- K4: normalize + ReLU + NHWC->NCHW ----------------
__global__ void __launch_bounds__(1024) k_apply(const float* __restrict__ gamma,
                                                const float* __restrict__ beta,
                                                float* __restrict__ out) {
    __shared__ float sm[32][33];
    int b = blockIdx.z;
    int o0 = blockIdx.y << 5;
    int pt = blockIdx.x << 5;
    int tx = threadIdx.x & 31, ty = threadIdx.x >> 5;
    sm[ty][tx] = g_y[(((b * HW) + pt + ty) << 8) + o0 + tx];
    __syncthreads();
    int o = o0 + ty;
    float mean = g_gn[(b * 32 + (o >> 3)) * 2];
    float rstd = g_gn[(b * 32 + (o >> 3)) * 2 + 1];
    float v = sm[tx][ty];
    v = (v - mean) * rstd * gamma[o] + beta[o];
    out[((size_t)(b * OO + o) << 12) + pt + tx] = fmaxf(v, 0.f);
}

// ---------------- launch ----------------
extern "C" void kernel_launch(void* const* d_in, const int* in_sizes, int n_in,
                              void* d_out, int out_size) {
    const float* x        = (const float*)d_in[0];
    const float* offset_w = (const float*)d_in[1];
    const float* offset_b = (const float*)d_in[2];
    const float* deform_w = (const float*)d_in[3];
    const float* gn_gamma = (const float*)d_in[4];
    const float* gn_beta  = (const float*)d_in[5];
    float* out = (float*)d_out;

    static int smem_set = 0;
    (void)smem_set;
    cudaFuncSetAttribute(k_deform, cudaFuncAttributeMaxDynamicSharedMemorySize, 67584);

    k_xt<<<dim3(8, 64, 4), 256>>>(x);
    k_wd<<<(KK * CC * OO + 255) / 256, 256>>>(deform_w);
    k_wo<<<(KK * CC * OCO + 255) / 256, 256>>>(offset_w);
    k_offconv<<<dim3(32, 4), 128>>>(offset_b);
    k_deform<<<dim3(64, 4), 256, 67584>>>();
    k_gnred<<<4, 1024>>>();
    k_apply<<<dim3(128, 8, 4), 1024>>>(gn_gamma, gn_beta, out);
}

// round 6
// speedup vs baseline: 4.2232x; 4.2232x over previous
#include <cuda_runtime.h>
#include <cstdint>

#define BB 4
#define CC 256
#define HH 64
#define WW 64
#define HW 4096
#define OCO 18
#define OO 256
#define GEPS 1e-5f

// ---------------- scratch ----------------
__device__ float g_xt[BB * HW * CC];        // x NHWC
__device__ float g_off[BB * HW * OCO];      // offsets NHWC
__device__ float g_wot[9 * 32 * CC];        // offset w [k][o(pad32)][c]
__device__ float g_wdt[9 * OO * CC];        // deform w [k][o][c]
__device__ float g_y[BB * HW * OO];         // pre-GN NHWC
__device__ float g_gnsum[BB * 32 * 2];      // per-(b,g) sum, sumsq
__device__ float g_gn[BB * 32 * 2];         // per-(b,g) mean, rstd

// ---------------- helpers ----------------
__device__ __forceinline__ float to_tf32(float x) {
    float r; asm("cvt.rna.tf32.f32 %0, %1;" : "=f"(r) : "f"(x)); return r;
}
__device__ __forceinline__ void mma_tf32(float* d, const uint32_t* a, const uint32_t* b) {
    asm volatile(
        "mma.sync.aligned.m16n8k8.row.col.f32.tf32.tf32.f32 "
        "{%0,%1,%2,%3}, {%4,%5,%6,%7}, {%8,%9}, {%0,%1,%2,%3};"
        : "+f"(d[0]), "+f"(d[1]), "+f"(d[2]), "+f"(d[3])
        : "r"(a[0]), "r"(a[1]), "r"(a[2]), "r"(a[3]), "r"(b[0]), "r"(b[1]));
}

// ---------------- K0: x NCHW -> NHWC ----------------
__global__ void k_xt(const float* __restrict__ x) {
    __shared__ float sm[32][65];
    int tid = threadIdx.x;
    int b = blockIdx.z, h = blockIdx.y, c0 = blockIdx.x * 32;
    for (int i = tid; i < 2048; i += 256) {
        int w = i & 63, c = i >> 6;
        sm[c][w] = x[((b * CC + c0 + c) * HH + h) * WW + w];
    }
    __syncthreads();
    for (int i = tid; i < 2048; i += 256) {
        int c = i & 31, w = i >> 5;
        g_xt[((b * HW + h * WW + w) << 8) + c0 + c] = sm[c][w];
    }
}

// ---------------- K0b: weight transposes + gnsum zero ----------------
#define N_WDT (9 * 256 * 256)
#define N_WOT (9 * 32 * 256)
__global__ void k_wt(const float* __restrict__ dw, const float* __restrict__ ow) {
    int idx = blockIdx.x * blockDim.x + threadIdx.x;
    if (idx < N_WDT) {
        int c = idx & 255, o = (idx >> 8) & 255, k = idx >> 16;
        g_wdt[idx] = to_tf32(dw[(o * 256 + c) * 9 + k]);
    } else if (idx < N_WDT + N_WOT) {
        int j = idx - N_WDT;
        int c = j & 255, o = (j >> 8) & 31, k = j >> 13;
        g_wot[j] = (o < OCO) ? to_tf32(ow[(o * 256 + c) * 9 + k]) : 0.f;
    } else if (idx < N_WDT + N_WOT + 256) {
        g_gnsum[idx - (N_WDT + N_WOT)] = 0.f;
    }
}

// ---------------- K1: offset conv via mma.sync tf32 ----------------
// CTA: 128 px (2 rows) x 32 outs (18 used). 8 warps, warp tile 32x16.
__global__ void __launch_bounds__(256) k_offc(const float* __restrict__ obias) {
    __shared__ float sA[128][36];
    __shared__ float sB[32][36];
    __shared__ int s_pi[128];

    int tid = threadIdx.x, lane = tid & 31, wid = tid >> 5;
    int b = blockIdx.y, y0 = blockIdx.x * 2;
    int wm = wid >> 1, wn = wid & 1;   // 4 M-tiles of 32, 2 N-tiles of 16

    float acc[2][2][4];
#pragma unroll
    for (int i = 0; i < 2; i++)
#pragma unroll
        for (int j = 0; j < 2; j++)
#pragma unroll
            for (int q = 0; q < 4; q++) acc[i][j][q] = 0.f;

    int c4 = tid & 7, pr = tid >> 3;

    for (int k = 0; k < 9; k++) {
        int ky = k / 3, kx = k % 3;
        __syncthreads();
        if (tid < 128) {
            int y = y0 + (tid >> 6), xx = tid & 63;
            int yy = y + ky - 1, xc = xx + kx - 1;
            bool v = ((unsigned)yy < 64u) && ((unsigned)xc < 64u);
            s_pi[tid] = v ? ((((b * HH + yy) << 6) + xc) << 8) : -1;
        }
        __syncthreads();
        for (int cc = 0; cc < 8; cc++) {
            int c0 = cc * 32;
            __syncthreads();
            // A: [128 px][32 c]
#pragma unroll
            for (int r = 0; r < 4; r++) {
                int p = pr + r * 32;
                int i0 = s_pi[p];
                float4 v = make_float4(0.f, 0.f, 0.f, 0.f);
                if (i0 >= 0) {
                    float4 a = *((const float4*)(g_xt + i0 + c0) + c4);
                    v.x = to_tf32(a.x); v.y = to_tf32(a.y);
                    v.z = to_tf32(a.z); v.w = to_tf32(a.w);
                }
                *(float4*)&sA[p][c4 * 4] = v;
            }
            // B: [32 o][32 c] (already tf32-rounded in g_wot)
            {
                int o = tid >> 3;
                float4 wv = *((const float4*)(g_wot + ((size_t)(k * 32 + o)) * 256 + c0) + c4);
                *(float4*)&sB[o][c4 * 4] = wv;
            }
            __syncthreads();
            // consume
#pragma unroll
            for (int ks = 0; ks < 4; ks++) {
                int kc = ks * 8 + (lane & 3);
                uint32_t af[2][4];
#pragma unroll
                for (int mt = 0; mt < 2; mt++) {
                    int r0 = wm * 32 + mt * 16 + (lane >> 2);
                    af[mt][0] = __float_as_uint(sA[r0][kc]);
                    af[mt][1] = __float_as_uint(sA[r0 + 8][kc]);
                    af[mt][2] = __float_as_uint(sA[r0][kc + 4]);
                    af[mt][3] = __float_as_uint(sA[r0 + 8][kc + 4]);
                }
#pragma unroll
                for (int nt = 0; nt < 2; nt++) {
                    int nn = wn * 16 + nt * 8 + (lane >> 2);
                    uint32_t bf[2];
                    bf[0] = __float_as_uint(sB[nn][kc]);
                    bf[1] = __float_as_uint(sB[nn][kc + 4]);
                    mma_tf32(acc[0][nt], af[0], bf);
                    mma_tf32(acc[1][nt], af[1], bf);
                }
            }
        }
    }
    // epilogue: g_off [px][18] + bias
#pragma unroll
    for (int mt = 0; mt < 2; mt++) {
#pragma unroll
        for (int nt = 0; nt < 2; nt++) {
            int p = wm * 32 + mt * 16 + (lane >> 2);
            int o = wn * 16 + nt * 8 + 2 * (lane & 3);
            if (o < OCO) {
                int y = y0 + (p >> 6), xx = p & 63;
                float* d0 = g_off + ((size_t)(b * HW) + y * 64 + xx) * OCO + o;
                d0[0] = acc[mt][nt][0] + obias[o];
                d0[1] = acc[mt][nt][1] + obias[o + 1];
                float* d1 = g_off + ((size_t)(b * HW) + ((p + 8) >> 6) * 64 + y0 * 64 // recompute below
                                     ) * OCO;  // placeholder, fixed next lines
                (void)d1;
                int p2 = p + 8;
                int y2 = y0 + (p2 >> 6), xx2 = p2 & 63;
                float* d2 = g_off + ((size_t)(b * HW) + y2 * 64 + xx2) * OCO + o;
                d2[0] = acc[mt][nt][2] + obias[o];
                d2[1] = acc[mt][nt][3] + obias[o + 1];
            }
        }
    }
}

// ---------------- K2: deformable conv via mma.sync tf32 ----------------
// CTA: 64 px (one row) x 256 outs. 8 warps, warp tile 32x64.
__global__ void __launch_bounds__(256) k_deform() {
    __shared__ float sA[64][36];
    __shared__ float sB[256][36];
    __shared__ float s_pw[4][64];
    __shared__ int s_pi[4][64];

    int tid = threadIdx.x, lane = tid & 31, wid = tid >> 5;
    int b = blockIdx.y, y = blockIdx.x;
    int wm = wid & 1, wn = wid >> 1;   // 2 M-tiles of 32, 4 N-tiles of 64

    float acc[2][8][4];
#pragma unroll
    for (int i = 0; i < 2; i++)
#pragma unroll
        for (int j = 0; j < 8; j++)
#pragma unroll
            for (int q = 0; q < 4; q++) acc[i][j][q] = 0.f;

    int c4 = tid & 7, pr = tid >> 3;

    for (int k = 0; k < 9; k++) {
        int ky = k / 3, kx = k % 3;
        __syncthreads();
        if (tid < 64) {
            int p = tid;
            const float* ob = g_off + ((size_t)(b * HW) + y * 64 + p) * OCO + 2 * k;
            float dy = ob[0], dx = ob[1];
            float py = (float)(y + ky - 1) + dy;
            float px = (float)(p + kx - 1) + dx;
            float yf = floorf(py), xf = floorf(px);
            float ty = py - yf, tx = px - xf;
            int iy = (int)yf, ix = (int)xf;
#pragma unroll
            for (int ci = 0; ci < 4; ci++) {
                int yy = iy + (ci >> 1), xc = ix + (ci & 1);
                float wy = (ci >> 1) ? ty : 1.f - ty;
                float wx = (ci & 1) ? tx : 1.f - tx;
                bool v = ((unsigned)yy < 64u) && ((unsigned)xc < 64u);
                s_pw[ci][p] = v ? wy * wx : 0.f;
                s_pi[ci][p] = (((b * HH + (v ? yy : 0)) << 6) + (v ? xc : 0)) << 8;
            }
        }
        __syncthreads();
        for (int cc = 0; cc < 8; cc++) {
            int c0 = cc * 32;
            __syncthreads();
            // A: bilinear-sampled [64 px][32 c]
#pragma unroll
            for (int r = 0; r < 2; r++) {
                int p = pr + r * 32;
                float w0 = s_pw[0][p], w1 = s_pw[1][p], w2 = s_pw[2][p], w3 = s_pw[3][p];
                float4 a0 = *((const float4*)(g_xt + s_pi[0][p] + c0) + c4);
                float4 a1 = *((const float4*)(g_xt + s_pi[1][p] + c0) + c4);
                float4 a2 = *((const float4*)(g_xt + s_pi[2][p] + c0) + c4);
                float4 a3 = *((const float4*)(g_xt + s_pi[3][p] + c0) + c4);
                float4 v;
                v.x = to_tf32(fmaf(w3, a3.x, fmaf(w2, a2.x, fmaf(w1, a1.x, w0 * a0.x))));
                v.y = to_tf32(fmaf(w3, a3.y, fmaf(w2, a2.y, fmaf(w1, a1.y, w0 * a0.y))));
                v.z = to_tf32(fmaf(w3, a3.z, fmaf(w2, a2.z, fmaf(w1, a1.z, w0 * a0.z))));
                v.w = to_tf32(fmaf(w3, a3.w, fmaf(w2, a2.w, fmaf(w1, a1.w, w0 * a0.w))));
                *(float4*)&sA[p][c4 * 4] = v;
            }
            // B: [256 o][32 c] (tf32-rounded already)
#pragma unroll
            for (int r = 0; r < 8; r++) {
                int o = pr + r * 32;
                float4 wv = *((const float4*)(g_wdt + ((size_t)(k * 256 + o)) * 256 + c0) + c4);
                *(float4*)&sB[o][c4 * 4] = wv;
            }
            __syncthreads();
            // consume: 4 k-steps x (2 m-tiles x 8 n-tiles)
#pragma unroll
            for (int ks = 0; ks < 4; ks++) {
                int kc = ks * 8 + (lane & 3);
                uint32_t af[2][4];
#pragma unroll
                for (int mt = 0; mt < 2; mt++) {
                    int r0 = wm * 32 + mt * 16 + (lane >> 2);
                    af[mt][0] = __float_as_uint(sA[r0][kc]);
                    af[mt][1] = __float_as_uint(sA[r0 + 8][kc]);
                    af[mt][2] = __float_as_uint(sA[r0][kc + 4]);
                    af[mt][3] = __float_as_uint(sA[r0 + 8][kc + 4]);
                }
#pragma unroll
                for (int nt = 0; nt < 8; nt++) {
                    int nn = wn * 64 + nt * 8 + (lane >> 2);
                    uint32_t bf[2];
                    bf[0] = __float_as_uint(sB[nn][kc]);
                    bf[1] = __float_as_uint(sB[nn][kc + 4]);
                    mma_tf32(acc[0][nt], af[0], bf);
                    mma_tf32(acc[1][nt], af[1], bf);
                }
            }
        }
    }
    // epilogue: g_y NHWC
    size_t rowbase = ((size_t)(b * HW) + y * 64);
#pragma unroll
    for (int mt = 0; mt < 2; mt++) {
        int p = wm * 32 + mt * 16 + (lane >> 2);
#pragma unroll
        for (int nt = 0; nt < 8; nt++) {
            int o = wn * 64 + nt * 8 + 2 * (lane & 3);
            float* d0 = g_y + (rowbase + p) * 256 + o;
            *(float2*)d0 = make_float2(acc[mt][nt][0], acc[mt][nt][1]);
            float* d1 = g_y + (rowbase + p + 8) * 256 + o;
            *(float2*)d1 = make_float2(acc[mt][nt][2], acc[mt][nt][3]);
        }
    }
}

// ---------------- K3: GN partial sums ----------------
__global__ void __launch_bounds__(256) k_gnred() {
    int bs = blockIdx.x >> 4, sl = blockIdx.x & 15;
    int o = threadIdx.x;
    const float* base = g_y + ((size_t)bs * HW + sl * 256) * 256 + o;
    float s = 0.f, q = 0.f;
    for (int p = 0; p < 256; p++) {
        float v = base[(size_t)p * 256];
        s += v;
        q = fmaf(v, v, q);
    }
    __shared__ float rs[256], rq[256];
    rs[o] = s; rq[o] = q;
    __syncthreads();
    if (o < 32) {
        float S = 0.f, Q = 0.f;
#pragma unroll
        for (int j = 0; j < 8; j++) { S += rs[o * 8 + j]; Q += rq[o * 8 + j]; }
        atomicAdd(&g_gnsum[(bs * 32 + o) * 2], S);
        atomicAdd(&g_gnsum[(bs * 32 + o) * 2 + 1], Q);
    }
}
__global__ void k_gnstat() {
    int i = threadIdx.x;
    if (i < 128) {
        float S = g_gnsum[i * 2], Q = g_gnsum[i * 2 + 1];
        const float inv = 1.f / 32768.f;
        float m = S * inv;
        float var = Q * inv - m * m;
        g_gn[i * 2] = m;
        g_gn[i * 2 + 1] = rsqrtf(var + GEPS);
    }
}

// ---------------- K4: normalize + ReLU + NHWC->NCHW ----------------
__global__ void __launch_bounds__(1024) k_apply(const float* __restrict__ gamma,
                                                const float* __restrict__ beta,
                                                float* __restrict__ out) {
    __shared__ float sm[32][33];
    int b = blockIdx.z;
    int o0 = blockIdx.y << 5;
    int pt = blockIdx.x << 5;
    int tx = threadIdx.x & 31, ty = threadIdx.x >> 5;
    sm[ty][tx] = g_y[(((b * HW) + pt + ty) << 8) + o0 + tx];
    __syncthreads();
    int o = o0 + ty;
    float mean = g_gn[(b * 32 + (o >> 3)) * 2];
    float rstd = g_gn[(b * 32 + (o >> 3)) * 2 + 1];
    float v = sm[tx][ty];
    v = (v - mean) * rstd * gamma[o] + beta[o];
    out[((size_t)(b * OO + o) << 12) + pt + tx] = fmaxf(v, 0.f);
}

// ---------------- launch ----------------
extern "C" void kernel_launch(void* const* d_in, const int* in_sizes, int n_in,
                              void* d_out, int out_size) {
    const float* x        = (const float*)d_in[0];
    const float* offset_w = (const float*)d_in[1];
    const float* offset_b = (const float*)d_in[2];
    const float* deform_w = (const float*)d_in[3];
    const float* gn_gamma = (const float*)d_in[4];
    const float* gn_beta  = (const float*)d_in[5];
    float* out = (float*)d_out;

    k_xt<<<dim3(8, 64, 4), 256>>>(x);
    k_wt<<<(N_WDT + N_WOT + 256 + 255) / 256, 256>>>(deform_w, offset_w);
    k_offc<<<dim3(32, 4), 256>>>(offset_b);
    k_deform<<<dim3(64, 4), 256>>>();
    k_gnred<<<64, 256>>>();
    k_gnstat<<<1, 128>>>();
    k_apply<<<dim3(128, 8, 4), 1024>>>(gn_gamma, gn_beta, out);
}

// round 8
// speedup vs baseline: 4.4102x; 1.0443x over previous
#include <cuda_runtime.h>
#include <cstdint>

#define BB 4
#define CC 256
#define HH 64
#define WW 64
#define HW 4096
#define OCO 18
#define OO 256
#define GEPS 1e-5f
#define SAW 36

// ---------------- scratch ----------------
__device__ float g_xt[BB * HW * CC];        // x NHWC
__device__ float g_off[BB * HW * OCO];      // offsets NHWC
__device__ float g_wot[9 * 32 * CC];        // offset w [k][o(pad32)][c]
__device__ float g_wdt[9 * OO * CC];        // deform w [k][o][c]
__device__ float g_y[BB * HW * OO];         // pre-GN NHWC
__device__ float g_gnsum[BB * 32 * 2];      // per-(b,g) sum, sumsq
__device__ float g_gn[BB * 32 * 2];         // per-(b,g) mean, rstd

// ---------------- helpers ----------------
__device__ __forceinline__ float to_tf32(float x) {
    float r; asm("cvt.rna.tf32.f32 %0, %1;" : "=f"(r) : "f"(x)); return r;
}
__device__ __forceinline__ void mma_tf32(float* d, const uint32_t* a, const uint32_t* b) {
    asm volatile(
        "mma.sync.aligned.m16n8k8.row.col.f32.tf32.tf32.f32 "
        "{%0,%1,%2,%3}, {%4,%5,%6,%7}, {%8,%9}, {%0,%1,%2,%3};"
        : "+f"(d[0]), "+f"(d[1]), "+f"(d[2]), "+f"(d[3])
        : "r"(a[0]), "r"(a[1]), "r"(a[2]), "r"(a[3]), "r"(b[0]), "r"(b[1]));
}
__device__ __forceinline__ void ldsm4(uint32_t& r0, uint32_t& r1, uint32_t& r2, uint32_t& r3,
                                      uint32_t addr) {
    asm volatile("ldmatrix.sync.aligned.m8n8.x4.shared.b16 {%0,%1,%2,%3}, [%4];"
                 : "=r"(r0), "=r"(r1), "=r"(r2), "=r"(r3) : "r"(addr));
}
__device__ __forceinline__ uint32_t smem_u32(const void* p) {
    uint32_t a;
    asm("{ .reg .u64 t; cvta.to.shared.u64 t, %1; cvt.u32.u64 %0, t; }" : "=r"(a) : "l"(p));
    return a;
}

// ---------------- K0: x NCHW -> NHWC ----------------
__global__ void k_xt(const float* __restrict__ x) {
    __shared__ float sm[32][65];
    int tid = threadIdx.x;
    int b = blockIdx.z, h = blockIdx.y, c0 = blockIdx.x * 32;
    for (int i = tid; i < 2048; i += 256) {
        int w = i & 63, c = i >> 6;
        sm[c][w] = x[((b * CC + c0 + c) * HH + h) * WW + w];
    }
    __syncthreads();
    for (int i = tid; i < 2048; i += 256) {
        int c = i & 31, w = i >> 5;
        g_xt[((b * HW + h * WW + w) << 8) + c0 + c] = sm[c][w];
    }
}

// ---------------- K0b: weight transposes + gnsum zero ----------------
#define N_WDT (9 * 256 * 256)
#define N_WOT (9 * 32 * 256)
__global__ void k_wt(const float* __restrict__ dw, const float* __restrict__ ow) {
    int idx = blockIdx.x * blockDim.x + threadIdx.x;
    if (idx < N_WDT) {
        int c = idx & 255, o = (idx >> 8) & 255, k = idx >> 16;
        g_wdt[idx] = to_tf32(dw[(o * 256 + c) * 9 + k]);
    } else if (idx < N_WDT + N_WOT) {
        int j = idx - N_WDT;
        int c = j & 255, o = (j >> 8) & 31, k = j >> 13;
        g_wot[j] = (o < OCO) ? to_tf32(ow[(o * 256 + c) * 9 + k]) : 0.f;
    } else if (idx < N_WDT + N_WOT + 256) {
        g_gnsum[idx - (N_WDT + N_WOT)] = 0.f;
    }
}

// ---------------- K1: offset conv (128 px x 32 outs, tf32 mma + ldmatrix) ----------------
__global__ void __launch_bounds__(256) k_offc(const float* __restrict__ obias) {
    __shared__ float sA[128][SAW];
    __shared__ float sB[32][SAW];
    __shared__ int s_pi[128];

    int tid = threadIdx.x, lane = tid & 31, wid = tid >> 5;
    int b = blockIdx.y, y0 = blockIdx.x * 2;
    int wm = wid >> 1, wn = wid & 1;
    int c4 = tid & 7, pr = tid >> 3;

    // ldmatrix per-lane address offsets
    int rowA = ((lane >> 3) & 1) * 8 + (lane & 7);
    int colA = (lane >> 4) * 4;
    int rowB = (lane >> 4) * 8 + (lane & 7);
    int colB = ((lane >> 3) & 1) * 4;
    uint32_t aBase[2], bBase;
#pragma unroll
    for (int mt = 0; mt < 2; mt++)
        aBase[mt] = smem_u32(sA) + (uint32_t)(((wm * 32 + mt * 16 + rowA) * SAW + colA) * 4);
    bBase = smem_u32(sB) + (uint32_t)(((wn * 16 + rowB) * SAW + colB) * 4);

    float acc[2][2][4];
#pragma unroll
    for (int i = 0; i < 2; i++)
#pragma unroll
        for (int j = 0; j < 2; j++)
#pragma unroll
            for (int q = 0; q < 4; q++) acc[i][j][q] = 0.f;

    for (int k = 0; k < 9; k++) {
        int ky = k / 3, kx = k % 3;
        __syncthreads();
        if (tid < 128) {
            int y = y0 + (tid >> 6), xx = tid & 63;
            int yy = y + ky - 1, xc = xx + kx - 1;
            bool v = ((unsigned)yy < 64u) && ((unsigned)xc < 64u);
            s_pi[tid] = v ? ((((b * HH + yy) << 6) + xc) << 8) : -1;
        }
        __syncthreads();
        for (int cc = 0; cc < 8; cc++) {
            int c0 = cc * 32;
            __syncthreads();
#pragma unroll
            for (int r = 0; r < 4; r++) {
                int p = pr + r * 32;
                int i0 = s_pi[p];
                float4 v = make_float4(0.f, 0.f, 0.f, 0.f);
                if (i0 >= 0) {
                    float4 a = *((const float4*)(g_xt + i0 + c0) + c4);
                    v.x = to_tf32(a.x); v.y = to_tf32(a.y);
                    v.z = to_tf32(a.z); v.w = to_tf32(a.w);
                }
                *(float4*)&sA[p][c4 * 4] = v;
            }
            {
                int o = tid >> 3;
                float4 wv = *((const float4*)(g_wot + ((size_t)(k * 32 + o)) * 256 + c0) + c4);
                *(float4*)&sB[o][c4 * 4] = wv;
            }
            __syncthreads();
#pragma unroll
            for (int ks = 0; ks < 4; ks++) {
                uint32_t af[2][4];
#pragma unroll
                for (int mt = 0; mt < 2; mt++)
                    ldsm4(af[mt][0], af[mt][1], af[mt][2], af[mt][3], aBase[mt] + ks * 32);
                uint32_t b0, b1, b2, b3;
                ldsm4(b0, b1, b2, b3, bBase + ks * 32);
                uint32_t bf0[2] = {b0, b1}, bf1[2] = {b2, b3};
                mma_tf32(acc[0][0], af[0], bf0);
                mma_tf32(acc[1][0], af[1], bf0);
                mma_tf32(acc[0][1], af[0], bf1);
                mma_tf32(acc[1][1], af[1], bf1);
            }
        }
    }
#pragma unroll
    for (int mt = 0; mt < 2; mt++) {
#pragma unroll
        for (int nt = 0; nt < 2; nt++) {
            int o = wn * 16 + nt * 8 + 2 * (lane & 3);
            if (o < OCO) {
                int p = wm * 32 + mt * 16 + (lane >> 2);
                int y = y0 + (p >> 6), xx = p & 63;
                float* d0 = g_off + ((size_t)(b * HW) + y * 64 + xx) * OCO + o;
                d0[0] = acc[mt][nt][0] + obias[o];
                d0[1] = acc[mt][nt][1] + obias[o + 1];
                int p2 = p + 8;
                int y2 = y0 + (p2 >> 6), xx2 = p2 & 63;
                float* d2 = g_off + ((size_t)(b * HW) + y2 * 64 + xx2) * OCO + o;
                d2[0] = acc[mt][nt][2] + obias[o];
                d2[1] = acc[mt][nt][3] + obias[o + 1];
            }
        }
    }
}

// ---------------- K2: deformable conv, double-buffered, ldmatrix, fused GN sums ----------
// dynamic smem layout (floats): sA0[64*36] sB0[256*36] sA1 sB1 pw[9*4*64] pi[9*4*64]
#define DBUF 11520              // floats per (sA,sB) buffer pair
#define PW_OFF (2 * DBUF)
#define PI_OFF (PW_OFF + 2304)
__global__ void __launch_bounds__(256, 2) k_deform() {
    extern __shared__ float dyn[];
    float* s_pw = dyn + PW_OFF;
    int* s_pi = (int*)(dyn + PI_OFF);

    int tid = threadIdx.x, lane = tid & 31, wid = tid >> 5;
    int b = blockIdx.y, y = blockIdx.x;
    int wm = wid & 1, wn = wid >> 1;
    int c4 = tid & 7, pr = tid >> 3;

    // precompute all 9 taps' bilinear params
    for (int idx = tid; idx < 9 * 64; idx += 256) {
        int k = idx >> 6, p = idx & 63;
        int ky = k / 3, kx = k % 3;
        const float* ob = g_off + ((size_t)(b * HW) + y * 64 + p) * OCO + 2 * k;
        float dy = ob[0], dx = ob[1];
        float py = (float)(y + ky - 1) + dy;
        float px = (float)(p + kx - 1) + dx;
        float yf = floorf(py), xf = floorf(px);
        float ty = py - yf, tx = px - xf;
        int iy = (int)yf, ix = (int)xf;
#pragma unroll
        for (int ci = 0; ci < 4; ci++) {
            int yy = iy + (ci >> 1), xc = ix + (ci & 1);
            float wy = (ci >> 1) ? ty : 1.f - ty;
            float wx = (ci & 1) ? tx : 1.f - tx;
            bool v = ((unsigned)yy < 64u) && ((unsigned)xc < 64u);
            s_pw[(k * 4 + ci) * 64 + p] = v ? wy * wx : 0.f;
            s_pi[(k * 4 + ci) * 64 + p] = (((b * HH + (v ? yy : 0)) << 6) + (v ? xc : 0)) << 8;
        }
    }

    // ldmatrix per-lane addresses (buffer 0; add bufByte per chunk)
    int rowA = ((lane >> 3) & 1) * 8 + (lane & 7);
    int colA = (lane >> 4) * 4;
    int rowB = (lane >> 4) * 8 + (lane & 7);
    int colB = ((lane >> 3) & 1) * 4;
    uint32_t sbase = smem_u32(dyn);
    uint32_t aBase[2], bBase[4];
#pragma unroll
    for (int mt = 0; mt < 2; mt++)
        aBase[mt] = sbase + (uint32_t)(((wm * 32 + mt * 16 + rowA) * SAW + colA) * 4);
#pragma unroll
    for (int j = 0; j < 4; j++)
        bBase[j] = sbase + (uint32_t)((2304 + (wn * 64 + j * 16 + rowB) * SAW + colB) * 4);

    float acc[2][8][4];
#pragma unroll
    for (int i = 0; i < 2; i++)
#pragma unroll
        for (int j = 0; j < 8; j++)
#pragma unroll
            for (int q = 0; q < 4; q++) acc[i][j][q] = 0.f;

    float4 ar[2][4];
    auto loadA = [&](int g) {
        int k = g >> 3, c0 = (g & 7) << 5;
        int base = k * 256 + pr;
#pragma unroll
        for (int r = 0; r < 2; r++) {
            int bi = base + r * 32;
#pragma unroll
            for (int ci = 0; ci < 4; ci++)
                ar[r][ci] = *((const float4*)(g_xt + s_pi[bi + ci * 64] + c0) + c4);
        }
    };
    auto storeAB = [&](int g) {
        int k = g >> 3, c0 = (g & 7) << 5;
        float* dA = dyn + (g & 1) * DBUF;
        float* dB = dA + 2304;
        int base = k * 256 + pr;
#pragma unroll
        for (int r = 0; r < 2; r++) {
            int p = pr + r * 32;
            int bi = base + r * 32;
            float w0 = s_pw[bi], w1 = s_pw[bi + 64], w2 = s_pw[bi + 128], w3 = s_pw[bi + 192];
            float4 v;
            v.x = to_tf32(fmaf(w3, ar[r][3].x, fmaf(w2, ar[r][2].x, fmaf(w1, ar[r][1].x, w0 * ar[r][0].x))));
            v.y = to_tf32(fmaf(w3, ar[r][3].y, fmaf(w2, ar[r][2].y, fmaf(w1, ar[r][1].y, w0 * ar[r][0].y))));
            v.z = to_tf32(fmaf(w3, ar[r][3].z, fmaf(w2, ar[r][2].z, fmaf(w1, ar[r][1].z, w0 * ar[r][0].z))));
            v.w = to_tf32(fmaf(w3, ar[r][3].w, fmaf(w2, ar[r][2].w, fmaf(w1, ar[r][1].w, w0 * ar[r][0].w))));
            *(float4*)&dA[p * SAW + c4 * 4] = v;
        }
#pragma unroll
        for (int r = 0; r < 8; r++) {
            int o = pr + r * 32;
            float4 wv = *((const float4*)(g_wdt + ((size_t)(k * 256 + o)) * 256 + c0) + c4);
            *(float4*)&dB[o * SAW + c4 * 4] = wv;
        }
    };

    __syncthreads();          // pw/pi visible
    loadA(0);
    storeAB(0);
    __syncthreads();

    for (int g = 0; g < 72; g++) {
        if (g < 71) loadA(g + 1);
        uint32_t bufByte = (uint32_t)(g & 1) * (DBUF * 4);
#pragma unroll
        for (int ks = 0; ks < 4; ks++) {
            uint32_t af[2][4];
#pragma unroll
            for (int mt = 0; mt < 2; mt++)
                ldsm4(af[mt][0], af[mt][1], af[mt][2], af[mt][3],
                      aBase[mt] + bufByte + ks * 32);
#pragma unroll
            for (int j = 0; j < 4; j++) {
                uint32_t b0, b1, b2, b3;
                ldsm4(b0, b1, b2, b3, bBase[j] + bufByte + ks * 32);
                uint32_t bf0[2] = {b0, b1}, bf1[2] = {b2, b3};
                mma_tf32(acc[0][2 * j], af[0], bf0);
                mma_tf32(acc[1][2 * j], af[1], bf0);
                mma_tf32(acc[0][2 * j + 1], af[0], bf1);
                mma_tf32(acc[1][2 * j + 1], af[1], bf1);
            }
        }
        if (g < 71) storeAB(g + 1);
        __syncthreads();
    }

    // epilogue: store g_y NHWC + fused GN partial sums
    size_t rowbase = ((size_t)(b * HW) + y * 64);
#pragma unroll
    for (int mt = 0; mt < 2; mt++) {
        int p = wm * 32 + mt * 16 + (lane >> 2);
#pragma unroll
        for (int nt = 0; nt < 8; nt++) {
            int o = wn * 64 + nt * 8 + 2 * (lane & 3);
            float* d0 = g_y + (rowbase + p) * 256 + o;
            *(float2*)d0 = make_float2(acc[mt][nt][0], acc[mt][nt][1]);
            float* d1 = g_y + (rowbase + p + 8) * 256 + o;
            *(float2*)d1 = make_float2(acc[mt][nt][2], acc[mt][nt][3]);
        }
    }
#pragma unroll
    for (int nt = 0; nt < 8; nt++) {
        float s = 0.f, q = 0.f;
#pragma unroll
        for (int mt = 0; mt < 2; mt++)
#pragma unroll
            for (int i = 0; i < 4; i++) {
                float v = acc[mt][nt][i];
                s += v;
                q = fmaf(v, v, q);
            }
#pragma unroll
        for (int off = 16; off; off >>= 1) {
            s += __shfl_xor_sync(0xFFFFFFFFu, s, off);
            q += __shfl_xor_sync(0xFFFFFFFFu, q, off);
        }
        if (lane == 0) {
            int grp = wn * 8 + nt;
            atomicAdd(&g_gnsum[(b * 32 + grp) * 2], s);
            atomicAdd(&g_gnsum[(b * 32 + grp) * 2 + 1], q);
        }
    }
}

// ---------------- K3: GN stats ----------------
__global__ void k_gnstat() {
    int i = threadIdx.x;
    if (i < 128) {
        float S = g_gnsum[i * 2], Q = g_gnsum[i * 2 + 1];
        const float inv = 1.f / 32768.f;
        float m = S * inv;
        float var = Q * inv - m * m;
        g_gn[i * 2] = m;
        g_gn[i * 2 + 1] = rsqrtf(var + GEPS);
    }
}

// ---------------- K4: normalize + ReLU + NHWC->NCHW ----------------
__global__ void __launch_bounds__(1024) k_apply(const float* __restrict__ gamma,
                                                const float* __restrict__ beta,
                                                float* __restrict__ out) {
    __shared__ float sm[32][33];
    int b = blockIdx.z;
    int o0 = blockIdx.y << 5;
    int pt = blockIdx.x << 5;
    int tx = threadIdx.x & 31, ty = threadIdx.x >> 5;
    sm[ty][tx] = g_y[(((b * HW) + pt + ty) << 8) + o0 + tx];
    __syncthreads();
    int o = o0 + ty;
    float mean = g_gn[(b * 32 + (o >> 3)) * 2];
    float rstd = g_gn[(b * 32 + (o >> 3)) * 2 + 1];
    float v = sm[tx][ty];
    v = (v - mean) * rstd * gamma[o] + beta[o];
    out[((size_t)(b * OO + o) << 12) + pt + tx] = fmaxf(v, 0.f);
}

// ---------------- launch ----------------
extern "C" void kernel_launch(void* const* d_in, const int* in_sizes, int n_in,
                              void* d_out, int out_size) {
    const float* x        = (const float*)d_in[0];
    const float* offset_w = (const float*)d_in[1];
    const float* offset_b = (const float*)d_in[2];
    const float* deform_w = (const float*)d_in[3];
    const float* gn_gamma = (const float*)d_in[4];
    const float* gn_beta  = (const float*)d_in[5];
    float* out = (float*)d_out;

    const int DSMEM = (PI_OFF + 2304) * 4;   // 110592 bytes
    cudaFuncSetAttribute(k_deform, cudaFuncAttributeMaxDynamicSharedMemorySize, DSMEM);

    k_xt<<<dim3(8, 64, 4), 256>>>(x);
    k_wt<<<(N_WDT + N_WOT + 256 + 255) / 256, 256>>>(deform_w, offset_w);
    k_offc<<<dim3(32, 4), 256>>>(offset_b);
    k_deform<<<dim3(64, 4), 256, DSMEM>>>();
    k_gnstat<<<1, 128>>>();
    k_apply<<<dim3(128, 8, 4), 1024>>>(gn_gamma, gn_beta, out);
}

// round 9
// speedup vs baseline: 7.2090x; 1.6346x over previous
#include <cuda_runtime.h>
#include <cuda_fp16.h>
#include <cstdint>

#define BB 4
#define CC 256
#define HH 64
#define WW 64
#define HW 4096
#define OCO 18
#define OO 256
#define GEPS 1e-5f
#define SAH 40   // smem row stride in halves (80B, conflict-free for ldsm)

// ---------------- scratch ----------------
__device__ __half g_xt[BB * HW * CC];        // x NHWC fp16 (8.4MB)
__device__ float  g_off[BB * HW * OCO];      // offsets NHWC fp32
__device__ __half g_wot[9 * 8 * 32 * 32];    // offset w [k][cc][o pad32][32c]
__device__ __half g_wdt[9 * 8 * 256 * 32];   // deform w [k][cc][o][32c]
__device__ float  g_y[BB * HW * OO];         // pre-GN NHWC
__device__ float  g_gnsum[BB * 32 * 2];
__device__ float  g_gn[BB * 32 * 2];

// ---------------- helpers ----------------
__device__ __forceinline__ void mma_f16(float* d, const uint32_t* a, uint32_t b0, uint32_t b1) {
    asm volatile(
        "mma.sync.aligned.m16n8k16.row.col.f32.f16.f16.f32 "
        "{%0,%1,%2,%3}, {%4,%5,%6,%7}, {%8,%9}, {%0,%1,%2,%3};"
        : "+f"(d[0]), "+f"(d[1]), "+f"(d[2]), "+f"(d[3])
        : "r"(a[0]), "r"(a[1]), "r"(a[2]), "r"(a[3]), "r"(b0), "r"(b1));
}
__device__ __forceinline__ void ldsm4(uint32_t& r0, uint32_t& r1, uint32_t& r2, uint32_t& r3,
                                      uint32_t addr) {
    asm volatile("ldmatrix.sync.aligned.m8n8.x4.shared.b16 {%0,%1,%2,%3}, [%4];"
                 : "=r"(r0), "=r"(r1), "=r"(r2), "=r"(r3) : "r"(addr));
}
__device__ __forceinline__ uint32_t smem_u32(const void* p) {
    uint32_t a;
    asm("{ .reg .u64 t; cvta.to.shared.u64 t, %1; cvt.u32.u64 %0, t; }" : "=r"(a) : "l"(p));
    return a;
}

// ---------------- K0: x NCHW -> NHWC (fp16) ----------------
__global__ void k_xt(const float* __restrict__ x) {
    __shared__ float sm[32][65];
    int tid = threadIdx.x;
    int b = blockIdx.z, h = blockIdx.y, c0 = blockIdx.x * 32;
    for (int i = tid; i < 2048; i += 256) {
        int w = i & 63, c = i >> 6;
        sm[c][w] = x[((b * CC + c0 + c) * HH + h) * WW + w];
    }
    __syncthreads();
    __half2* dst = (__half2*)g_xt;
    for (int i = tid; i < 1024; i += 256) {
        int w = i >> 4, cp = i & 15;
        dst[(((size_t)(b * HW) + h * 64 + w) << 7) + (c0 >> 1) + cp] =
            __floats2half2_rn(sm[cp * 2][w], sm[cp * 2 + 1][w]);
    }
}

// ---------------- K0b: weight transposes (chunk-major fp16) + gnsum zero ----------------
#define N_WDT (9 * 8 * 256 * 32)
#define N_WOT (9 * 8 * 32 * 32)
__global__ void k_wt(const float* __restrict__ dw, const float* __restrict__ ow) {
    int idx = blockIdx.x * blockDim.x + threadIdx.x;
    if (idx < N_WDT) {
        int inner = idx & 31, o = (idx >> 5) & 255, cc = (idx >> 13) & 7, k = idx >> 16;
        int c = cc * 32 + inner;
        g_wdt[idx] = __float2half_rn(dw[(o * 256 + c) * 9 + k]);
    } else if (idx < N_WDT + N_WOT) {
        int j = idx - N_WDT;
        int inner = j & 31, o = (j >> 5) & 31, cc = (j >> 10) & 7, k = j >> 13;
        int c = cc * 32 + inner;
        g_wot[j] = (o < OCO) ? __float2half_rn(ow[(o * 256 + c) * 9 + k]) : __float2half_rn(0.f);
    } else if (idx < N_WDT + N_WOT + 256) {
        g_gnsum[idx - (N_WDT + N_WOT)] = 0.f;
    }
}

// ---------------- K1: offset conv (128 px x 32 outs, fp16 mma) ----------------
__global__ void __launch_bounds__(256) k_offc(const float* __restrict__ obias) {
    __shared__ __half sA[128][SAH];
    __shared__ __half sB[32][SAH];
    __shared__ int s_pi[128];

    int tid = threadIdx.x, lane = tid & 31, wid = tid >> 5;
    int b = blockIdx.y, y0 = blockIdx.x * 2;
    int wm = wid >> 1, wn = wid & 1;

    // fragment addresses
    uint32_t aBase[2], bBase;
#pragma unroll
    for (int mt = 0; mt < 2; mt++)
        aBase[mt] = smem_u32(sA)
                  + (uint32_t)((wm * 32 + mt * 16 + (lane & 15)) * (SAH * 2) + (lane >> 4) * 16);
    bBase = smem_u32(sB)
          + (uint32_t)((wn * 16 + (lane & 7) + (lane >> 4) * 8) * (SAH * 2) + ((lane >> 3) & 1) * 16);

    float acc[2][2][4];
#pragma unroll
    for (int i = 0; i < 2; i++)
#pragma unroll
        for (int j = 0; j < 2; j++)
#pragma unroll
            for (int q = 0; q < 4; q++) acc[i][j][q] = 0.f;

    int px = tid >> 1, sg = tid & 1;     // A staging: 128 px, 2 x 16-half segments

    for (int k = 0; k < 9; k++) {
        int ky = k / 3, kx = k % 3;
        __syncthreads();
        if (tid < 128) {
            int y = y0 + (tid >> 6), xx = tid & 63;
            int yy = y + ky - 1, xc = xx + kx - 1;
            bool v = ((unsigned)yy < 64u) && ((unsigned)xc < 64u);
            s_pi[tid] = v ? ((((b * HH + yy) << 6) + xc) << 8) : -1;
        }
        __syncthreads();
        for (int cc = 0; cc < 8; cc++) {
            int c0 = cc * 32;
            __syncthreads();
            {   // A: [128 px][32 c] halves
                int i0 = s_pi[px];
                uint4 v0 = make_uint4(0, 0, 0, 0), v1 = v0;
                if (i0 >= 0) {
                    const uint4* src = (const uint4*)(g_xt + i0 + c0 + sg * 16);
                    v0 = src[0]; v1 = src[1];
                }
                *(uint4*)&sA[px][sg * 16] = v0;
                *(uint4*)&sA[px][sg * 16 + 8] = v1;
            }
            if (tid < 128) {  // B: [32 o][32 c]
                int o = tid >> 2, s2 = tid & 3;
                const uint4* src = (const uint4*)(g_wot + ((size_t)(k * 8 + cc)) * 1024 + o * 32 + s2 * 8);
                *(uint4*)&sB[o][s2 * 8] = src[0];
            }
            __syncthreads();
#pragma unroll
            for (int ks = 0; ks < 2; ks++) {
                uint32_t af[2][4];
#pragma unroll
                for (int mt = 0; mt < 2; mt++)
                    ldsm4(af[mt][0], af[mt][1], af[mt][2], af[mt][3], aBase[mt] + ks * 32);
                uint32_t b0, b1, b2, b3;
                ldsm4(b0, b1, b2, b3, bBase + ks * 32);
                mma_f16(acc[0][0], af[0], b0, b1);
                mma_f16(acc[1][0], af[1], b0, b1);
                mma_f16(acc[0][1], af[0], b2, b3);
                mma_f16(acc[1][1], af[1], b2, b3);
            }
        }
    }
#pragma unroll
    for (int mt = 0; mt < 2; mt++) {
#pragma unroll
        for (int nt = 0; nt < 2; nt++) {
            int o = wn * 16 + nt * 8 + 2 * (lane & 3);
            if (o < OCO) {
                int p = wm * 32 + mt * 16 + (lane >> 2);
                int y = y0 + (p >> 6), xx = p & 63;
                float* d0 = g_off + ((size_t)(b * HW) + y * 64 + xx) * OCO + o;
                d0[0] = acc[mt][nt][0] + obias[o];
                d0[1] = acc[mt][nt][1] + obias[o + 1];
                int p2 = p + 8;
                int y2 = y0 + (p2 >> 6), xx2 = p2 & 63;
                float* d2 = g_off + ((size_t)(b * HW) + y2 * 64 + xx2) * OCO + o;
                d2[0] = acc[mt][nt][2] + obias[o];
                d2[1] = acc[mt][nt][3] + obias[o + 1];
            }
        }
    }
}

// ---------------- K2: deformable conv fp16, double-buffered, fused GN ----------
// dyn smem bytes: [buf0: A 64x40h (5120) | B 256x40h (20480)] [buf1 ...] [pw 9216] [pi 9216]
#define ABUF_B 5120
#define DBUF_B 25600
#define PW_B   51200
#define PI_B   60416
#define DSMEM_TOT 69632
__global__ void __launch_bounds__(256, 2) k_deform() {
    extern __shared__ char dyn[];
    float* s_pw = (float*)(dyn + PW_B);
    int* s_pi = (int*)(dyn + PI_B);

    int tid = threadIdx.x, lane = tid & 31, wid = tid >> 5;
    int b = blockIdx.y, y = blockIdx.x;
    int wm = wid & 1, wn = wid >> 1;
    int px = tid >> 2, sg = tid & 3;    // A staging: 64 px x 4 segs of 8 halves

    // precompute all 9 taps' bilinear params
    for (int idx = tid; idx < 9 * 64; idx += 256) {
        int k = idx >> 6, p = idx & 63;
        int ky = k / 3, kx = k % 3;
        const float* ob = g_off + ((size_t)(b * HW) + y * 64 + p) * OCO + 2 * k;
        float dy = ob[0], dx = ob[1];
        float py = (float)(y + ky - 1) + dy;
        float pxx = (float)(p + kx - 1) + dx;
        float yf = floorf(py), xf = floorf(pxx);
        float ty = py - yf, tx = pxx - xf;
        int iy = (int)yf, ix = (int)xf;
#pragma unroll
        for (int ci = 0; ci < 4; ci++) {
            int yy = iy + (ci >> 1), xc = ix + (ci & 1);
            float wy = (ci >> 1) ? ty : 1.f - ty;
            float wx = (ci & 1) ? tx : 1.f - tx;
            bool v = ((unsigned)yy < 64u) && ((unsigned)xc < 64u);
            s_pw[(k * 4 + ci) * 64 + p] = v ? wy * wx : 0.f;
            s_pi[(k * 4 + ci) * 64 + p] = (((b * HH + (v ? yy : 0)) << 6) + (v ? xc : 0)) << 8;
        }
    }

    // fragment addresses (buffer 0; add bufByte per chunk)
    uint32_t sbase = smem_u32(dyn);
    uint32_t aBase[2], bBase[4];
#pragma unroll
    for (int mt = 0; mt < 2; mt++)
        aBase[mt] = sbase + (uint32_t)((wm * 32 + mt * 16 + (lane & 15)) * (SAH * 2) + (lane >> 4) * 16);
#pragma unroll
    for (int j = 0; j < 4; j++)
        bBase[j] = sbase + ABUF_B
                 + (uint32_t)((wn * 64 + j * 16 + (lane & 7) + (lane >> 4) * 8) * (SAH * 2)
                              + ((lane >> 3) & 1) * 16);

    float acc[2][8][4];
#pragma unroll
    for (int i = 0; i < 2; i++)
#pragma unroll
        for (int j = 0; j < 8; j++)
#pragma unroll
            for (int q = 0; q < 4; q++) acc[i][j][q] = 0.f;

    uint4 au[4], bu[4];
    auto loadAB = [&](int g) {
        int k = g >> 3, c0 = (g & 7) << 5;
        int base = k * 256 + px;   // (k*4+ci)*64 + px  with ci stride 64
#pragma unroll
        for (int ci = 0; ci < 4; ci++)
            au[ci] = *(const uint4*)(g_xt + s_pi[base + ci * 64] + c0 + sg * 8);
        const __half* wb = g_wdt + ((size_t)g) * 8192;   // chunk-major [g][o][32c]
#pragma unroll
        for (int j = 0; j < 4; j++)
            bu[j] = *(const uint4*)(wb + tid * 32 + j * 8);
    };
    auto storeAB = [&](int g) {
        int k = g >> 3;
        char* dA = dyn + (g & 1) * DBUF_B;
        char* dB = dA + ABUF_B;
        int base = k * 256 + px;
        float w0 = s_pw[base], w1 = s_pw[base + 64], w2 = s_pw[base + 128], w3 = s_pw[base + 192];
        uint4 out;
        __half2* ho = (__half2*)&out;
#pragma unroll
        for (int q = 0; q < 4; q++) {
            float2 f0 = __half22float2(((const __half2*)&au[0])[q]);
            float2 f1 = __half22float2(((const __half2*)&au[1])[q]);
            float2 f2 = __half22float2(((const __half2*)&au[2])[q]);
            float2 f3 = __half22float2(((const __half2*)&au[3])[q]);
            float rx = fmaf(w3, f3.x, fmaf(w2, f2.x, fmaf(w1, f1.x, w0 * f0.x)));
            float ry = fmaf(w3, f3.y, fmaf(w2, f2.y, fmaf(w1, f1.y, w0 * f0.y)));
            ho[q] = __floats2half2_rn(rx, ry);
        }
        *(uint4*)(dA + px * (SAH * 2) + sg * 16) = out;
#pragma unroll
        for (int j = 0; j < 4; j++)
            *(uint4*)(dB + tid * (SAH * 2) + j * 16) = bu[j];
    };

    __syncthreads();
    loadAB(0);
    storeAB(0);
    __syncthreads();

    for (int g = 0; g < 72; g++) {
        if (g < 71) loadAB(g + 1);
        uint32_t bufByte = (uint32_t)(g & 1) * DBUF_B;
#pragma unroll
        for (int ks = 0; ks < 2; ks++) {
            uint32_t af[2][4];
#pragma unroll
            for (int mt = 0; mt < 2; mt++)
                ldsm4(af[mt][0], af[mt][1], af[mt][2], af[mt][3], aBase[mt] + bufByte + ks * 32);
#pragma unroll
            for (int j = 0; j < 4; j++) {
                uint32_t b0, b1, b2, b3;
                ldsm4(b0, b1, b2, b3, bBase[j] + bufByte + ks * 32);
                mma_f16(acc[0][2 * j], af[0], b0, b1);
                mma_f16(acc[1][2 * j], af[1], b0, b1);
                mma_f16(acc[0][2 * j + 1], af[0], b2, b3);
                mma_f16(acc[1][2 * j + 1], af[1], b2, b3);
            }
        }
        if (g < 71) storeAB(g + 1);
        __syncthreads();
    }

    // epilogue: store g_y NHWC + fused GN partial sums
    size_t rowbase = ((size_t)(b * HW) + y * 64);
#pragma unroll
    for (int mt = 0; mt < 2; mt++) {
        int p = wm * 32 + mt * 16 + (lane >> 2);
#pragma unroll
        for (int nt = 0; nt < 8; nt++) {
            int o = wn * 64 + nt * 8 + 2 * (lane & 3);
            float* d0 = g_y + (rowbase + p) * 256 + o;
            *(float2*)d0 = make_float2(acc[mt][nt][0], acc[mt][nt][1]);
            float* d1 = g_y + (rowbase + p + 8) * 256 + o;
            *(float2*)d1 = make_float2(acc[mt][nt][2], acc[mt][nt][3]);
        }
    }
#pragma unroll
    for (int nt = 0; nt < 8; nt++) {
        float s = 0.f, q = 0.f;
#pragma unroll
        for (int mt = 0; mt < 2; mt++)
#pragma unroll
            for (int i = 0; i < 4; i++) {
                float v = acc[mt][nt][i];
                s += v;
                q = fmaf(v, v, q);
            }
#pragma unroll
        for (int off = 16; off; off >>= 1) {
            s += __shfl_xor_sync(0xFFFFFFFFu, s, off);
            q += __shfl_xor_sync(0xFFFFFFFFu, q, off);
        }
        if (lane == 0) {
            int grp = wn * 8 + nt;
            atomicAdd(&g_gnsum[(b * 32 + grp) * 2], s);
            atomicAdd(&g_gnsum[(b * 32 + grp) * 2 + 1], q);
        }
    }
}

// ---------------- K3: GN stats ----------------
__global__ void k_gnstat() {
    int i = threadIdx.x;
    if (i < 128) {
        float S = g_gnsum[i * 2], Q = g_gnsum[i * 2 + 1];
        const float inv = 1.f / 32768.f;
        float m = S * inv;
        float var = Q * inv - m * m;
        g_gn[i * 2] = m;
        g_gn[i * 2 + 1] = rsqrtf(var + GEPS);
    }
}

// ---------------- K4: normalize + ReLU + NHWC->NCHW ----------------
__global__ void __launch_bounds__(1024) k_apply(const float* __restrict__ gamma,
                                                const float* __restrict__ beta,
                                                float* __restrict__ out) {
    __shared__ float sm[32][33];
    int b = blockIdx.z;
    int o0 = blockIdx.y << 5;
    int pt = blockIdx.x << 5;
    int tx = threadIdx.x & 31, ty = threadIdx.x >> 5;
    sm[ty][tx] = g_y[(((b * HW) + pt + ty) << 8) + o0 + tx];
    __syncthreads();
    int o = o0 + ty;
    float mean = g_gn[(b * 32 + (o >> 3)) * 2];
    float rstd = g_gn[(b * 32 + (o >> 3)) * 2 + 1];
    float v = sm[tx][ty];
    v = (v - mean) * rstd * gamma[o] + beta[o];
    out[((size_t)(b * OO + o) << 12) + pt + tx] = fmaxf(v, 0.f);
}

// ---------------- launch ----------------
extern "C" void kernel_launch(void* const* d_in, const int* in_sizes, int n_in,
                              void* d_out, int out_size) {
    const float* x        = (const float*)d_in[0];
    const float* offset_w = (const float*)d_in[1];
    const float* offset_b = (const float*)d_in[2];
    const float* deform_w = (const float*)d_in[3];
    const float* gn_gamma = (const float*)d_in[4];
    const float* gn_beta  = (const float*)d_in[5];
    float* out = (float*)d_out;

    cudaFuncSetAttribute(k_deform, cudaFuncAttributeMaxDynamicSharedMemorySize, DSMEM_TOT);

    k_xt<<<dim3(8, 64, 4), 256>>>(x);
    k_wt<<<(N_WDT + N_WOT + 256 + 255) / 256, 256>>>(deform_w, offset_w);
    k_offc<<<dim3(32, 4), 256>>>(offset_b);
    k_deform<<<dim3(64, 4), 256, DSMEM_TOT>>>();
    k_gnstat<<<1, 128>>>();
    k_apply<<<dim3(128, 8, 4), 1024>>>(gn_gamma, gn_beta, out);
}

// round 11
// speedup vs baseline: 7.3750x; 1.0230x over previous
#include <cuda_runtime.h>
#include <cuda_fp16.h>
#include <cstdint>

#define BB 4
#define CC 256
#define HH 64
#define WW 64
#define HW 4096
#define OCO 18
#define OO 256
#define GEPS 1e-5f
#define SAH 40   // smem row stride in halves (80B)

// ---------------- scratch ----------------
__device__ __half g_xt[BB * HW * CC];        // x NHWC fp16
__device__ float  g_off[BB * HW * OCO];      // offsets NHWC fp32
__device__ __half g_wot[9 * 8 * 32 * 32];    // offset w [k][cc][o pad32][32c]
__device__ __half g_wdt[9 * 8 * 256 * 32];   // deform w [k][cc][o][32c]
__device__ float  g_y[BB * HW * OO];         // pre-GN NHWC
__device__ float  g_gnsum[BB * 32 * 2];
__device__ float  g_gn[BB * 32 * 2];

// ---------------- helpers ----------------
__device__ __forceinline__ void mma_f16(float* d, const uint32_t* a, uint32_t b0, uint32_t b1) {
    asm volatile(
        "mma.sync.aligned.m16n8k16.row.col.f32.f16.f16.f32 "
        "{%0,%1,%2,%3}, {%4,%5,%6,%7}, {%8,%9}, {%0,%1,%2,%3};"
        : "+f"(d[0]), "+f"(d[1]), "+f"(d[2]), "+f"(d[3])
        : "r"(a[0]), "r"(a[1]), "r"(a[2]), "r"(a[3]), "r"(b0), "r"(b1));
}
__device__ __forceinline__ void ldsm4(uint32_t& r0, uint32_t& r1, uint32_t& r2, uint32_t& r3,
                                      uint32_t addr) {
    asm volatile("ldmatrix.sync.aligned.m8n8.x4.shared.b16 {%0,%1,%2,%3}, [%4];"
                 : "=r"(r0), "=r"(r1), "=r"(r2), "=r"(r3) : "r"(addr));
}
__device__ __forceinline__ uint32_t smem_u32(const void* p) {
    uint32_t a;
    asm("{ .reg .u64 t; cvta.to.shared.u64 t, %1; cvt.u32.u64 %0, t; }" : "=r"(a) : "l"(p));
    return a;
}
__device__ __forceinline__ void cp16(uint32_t dst, const void* src) {
    asm volatile("cp.async.cg.shared.global [%0], [%1], 16;" :: "r"(dst), "l"(src) : "memory");
}
#define CP_COMMIT() asm volatile("cp.async.commit_group;" ::: "memory")
#define CP_WAIT0()  asm volatile("cp.async.wait_group 0;" ::: "memory")

// ---------------- K0: x NCHW -> NHWC (fp16) ----------------
__global__ void k_xt(const float* __restrict__ x) {
    __shared__ float sm[32][65];
    int tid = threadIdx.x;
    int b = blockIdx.z, h = blockIdx.y, c0 = blockIdx.x * 32;
    for (int i = tid; i < 2048; i += 256) {
        int w = i & 63, c = i >> 6;
        sm[c][w] = x[((b * CC + c0 + c) * HH + h) * WW + w];
    }
    __syncthreads();
    __half2* dst = (__half2*)g_xt;
    for (int i = tid; i < 1024; i += 256) {
        int w = i >> 4, cp = i & 15;
        dst[(((size_t)(b * HW) + h * 64 + w) << 7) + (c0 >> 1) + cp] =
            __floats2half2_rn(sm[cp * 2][w], sm[cp * 2 + 1][w]);
    }
}

// ---------------- K0b: weight transposes (chunk-major fp16) + gnsum zero ----------------
#define N_WDT (9 * 8 * 256 * 32)
#define N_WOT (9 * 8 * 32 * 32)
__global__ void k_wt(const float* __restrict__ dw, const float* __restrict__ ow) {
    int idx = blockIdx.x * blockDim.x + threadIdx.x;
    if (idx < N_WDT) {
        int inner = idx & 31, o = (idx >> 5) & 255, cc = (idx >> 13) & 7, k = idx >> 16;
        int c = cc * 32 + inner;
        g_wdt[idx] = __float2half_rn(dw[(o * 256 + c) * 9 + k]);
    } else if (idx < N_WDT + N_WOT) {
        int j = idx - N_WDT;
        int inner = j & 31, o = (j >> 5) & 31, cc = (j >> 10) & 7, k = j >> 13;
        int c = cc * 32 + inner;
        g_wot[j] = (o < OCO) ? __float2half_rn(ow[(o * 256 + c) * 9 + k]) : __float2half_rn(0.f);
    } else if (idx < N_WDT + N_WOT + 256) {
        g_gnsum[idx - (N_WDT + N_WOT)] = 0.f;
    }
}

// ---------------- K1: offset conv (128 px x 32 outs, fp16 mma) ----------------
__global__ void __launch_bounds__(256) k_offc(const float* __restrict__ obias) {
    __shared__ __half sA[128][SAH];
    __shared__ __half sB[32][SAH];
    __shared__ int s_pi[128];

    int tid = threadIdx.x, lane = tid & 31, wid = tid >> 5;
    int b = blockIdx.y, y0 = blockIdx.x * 2;
    int wm = wid >> 1, wn = wid & 1;

    uint32_t aBase[2], bBase;
#pragma unroll
    for (int mt = 0; mt < 2; mt++)
        aBase[mt] = smem_u32(sA)
                  + (uint32_t)((wm * 32 + mt * 16 + (lane & 15)) * (SAH * 2) + (lane >> 4) * 16);
    bBase = smem_u32(sB)
          + (uint32_t)((wn * 16 + (lane & 7) + (lane >> 4) * 8) * (SAH * 2) + ((lane >> 3) & 1) * 16);

    float acc[2][2][4];
#pragma unroll
    for (int i = 0; i < 2; i++)
#pragma unroll
        for (int j = 0; j < 2; j++)
#pragma unroll
            for (int q = 0; q < 4; q++) acc[i][j][q] = 0.f;

    int px = tid >> 1, sg = tid & 1;

    for (int k = 0; k < 9; k++) {
        int ky = k / 3, kx = k % 3;
        __syncthreads();
        if (tid < 128) {
            int y = y0 + (tid >> 6), xx = tid & 63;
            int yy = y + ky - 1, xc = xx + kx - 1;
            bool v = ((unsigned)yy < 64u) && ((unsigned)xc < 64u);
            s_pi[tid] = v ? ((((b * HH + yy) << 6) + xc) << 8) : -1;
        }
        __syncthreads();
        for (int cc = 0; cc < 8; cc++) {
            int c0 = cc * 32;
            __syncthreads();
            {
                int i0 = s_pi[px];
                uint4 v0 = make_uint4(0, 0, 0, 0), v1 = v0;
                if (i0 >= 0) {
                    const uint4* src = (const uint4*)(g_xt + i0 + c0 + sg * 16);
                    v0 = src[0]; v1 = src[1];
                }
                *(uint4*)&sA[px][sg * 16] = v0;
                *(uint4*)&sA[px][sg * 16 + 8] = v1;
            }
            if (tid < 128) {
                int o = tid >> 2, s2 = tid & 3;
                const uint4* src = (const uint4*)(g_wot + ((size_t)(k * 8 + cc)) * 1024 + o * 32 + s2 * 8);
                *(uint4*)&sB[o][s2 * 8] = src[0];
            }
            __syncthreads();
#pragma unroll
            for (int ks = 0; ks < 2; ks++) {
                uint32_t af[2][4];
#pragma unroll
                for (int mt = 0; mt < 2; mt++)
                    ldsm4(af[mt][0], af[mt][1], af[mt][2], af[mt][3], aBase[mt] + ks * 32);
                uint32_t b0, b1, b2, b3;
                ldsm4(b0, b1, b2, b3, bBase + ks * 32);
                mma_f16(acc[0][0], af[0], b0, b1);
                mma_f16(acc[1][0], af[1], b0, b1);
                mma_f16(acc[0][1], af[0], b2, b3);
                mma_f16(acc[1][1], af[1], b2, b3);
            }
        }
    }
#pragma unroll
    for (int mt = 0; mt < 2; mt++) {
#pragma unroll
        for (int nt = 0; nt < 2; nt++) {
            int o = wn * 16 + nt * 8 + 2 * (lane & 3);
            if (o < OCO) {
                int p = wm * 32 + mt * 16 + (lane >> 2);
                int y = y0 + (p >> 6), xx = p & 63;
                float* d0 = g_off + ((size_t)(b * HW) + y * 64 + xx) * OCO + o;
                d0[0] = acc[mt][nt][0] + obias[o];
                d0[1] = acc[mt][nt][1] + obias[o + 1];
                int p2 = p + 8;
                int y2 = y0 + (p2 >> 6), xx2 = p2 & 63;
                float* d2 = g_off + ((size_t)(b * HW) + y2 * 64 + xx2) * OCO + o;
                d2[0] = acc[mt][nt][2] + obias[o];
                d2[1] = acc[mt][nt][3] + obias[o + 1];
            }
        }
    }
}

// ---------------- K2: deformable conv fp16, M=128, cp.async B, fused GN ----------
// smem bytes: buf{0,1}: [A 128x40h = 10240 | B 256x40h = 20480] ; pw 18432 ; pi 18432
#define ABUF_B 10240
#define DBUF_B 30720
#define PW_B   61440
#define PI_B   79872
#define DSMEM_TOT 98304
__global__ void __launch_bounds__(512, 1) k_deform() {
    extern __shared__ char dyn[];
    float* s_pw = (float*)(dyn + PW_B);
    int* s_pi = (int*)(dyn + PI_B);

    int tid = threadIdx.x, lane = tid & 31, wid = tid >> 5;
    int b = blockIdx.y, y0 = blockIdx.x * 2;
    int wm = wid & 3, wn = wid >> 2;           // 4 M-tiles of 32, 4 N-tiles of 64
    int px = tid >> 2, sg = tid & 3;           // A staging: 128 px x 4 segs of 8 halves

    // precompute all 9 taps' bilinear params for 128 px
    for (int idx = tid; idx < 9 * 128; idx += 512) {
        int k = idx >> 7, p = idx & 127;
        int ky = k / 3, kx = k % 3;
        int y = y0 + (p >> 6), xx = p & 63;
        const float* ob = g_off + ((size_t)(b * HW) + y * 64 + xx) * OCO + 2 * k;
        float dy = ob[0], dx = ob[1];
        float py = (float)(y + ky - 1) + dy;
        float pxx = (float)(xx + kx - 1) + dx;
        float yf = floorf(py), xf = floorf(pxx);
        float ty = py - yf, tx = pxx - xf;
        int iy = (int)yf, ix = (int)xf;
#pragma unroll
        for (int ci = 0; ci < 4; ci++) {
            int yy = iy + (ci >> 1), xc = ix + (ci & 1);
            float wy = (ci >> 1) ? ty : 1.f - ty;
            float wx = (ci & 1) ? tx : 1.f - tx;
            bool v = ((unsigned)yy < 64u) && ((unsigned)xc < 64u);
            s_pw[(k * 4 + ci) * 128 + p] = v ? wy * wx : 0.f;
            s_pi[(k * 4 + ci) * 128 + p] = (((b * HH + (v ? yy : 0)) << 6) + (v ? xc : 0)) << 8;
        }
    }

    // fragment addresses (buffer 0; add bufByte per chunk)
    uint32_t sbase = smem_u32(dyn);
    uint32_t aBase[2], bBase[4];
#pragma unroll
    for (int mt = 0; mt < 2; mt++)
        aBase[mt] = sbase + (uint32_t)((wm * 32 + mt * 16 + (lane & 15)) * (SAH * 2) + (lane >> 4) * 16);
#pragma unroll
    for (int j = 0; j < 4; j++)
        bBase[j] = sbase + ABUF_B
                 + (uint32_t)((wn * 64 + j * 16 + (lane & 7) + (lane >> 4) * 8) * (SAH * 2)
                              + ((lane >> 3) & 1) * 16);

    // cp.async B mapping: 2 segs per thread
    int bo0 = tid >> 1, bs0 = (tid & 1) * 2;   // (o, seg) pairs: (tid>>1, 2*(tid&1)) and +1
    uint32_t bDst0 = sbase + ABUF_B + (uint32_t)(bo0 * (SAH * 2) + bs0 * 16);

    float acc[2][8][4];
#pragma unroll
    for (int i = 0; i < 2; i++)
#pragma unroll
        for (int j = 0; j < 8; j++)
#pragma unroll
            for (int q = 0; q < 4; q++) acc[i][j][q] = 0.f;

    uint4 au[4];
    auto loadA = [&](int g) {
        int k = g >> 3, c0 = (g & 7) << 5;
        int base = k * 512 + px;
#pragma unroll
        for (int ci = 0; ci < 4; ci++)
            au[ci] = *(const uint4*)(g_xt + s_pi[base + ci * 128] + c0 + sg * 8);
    };
    auto cpB = [&](int g) {
        const __half* wb = g_wdt + ((size_t)g) * 8192;
        uint32_t dst = bDst0 + (uint32_t)(g & 1) * DBUF_B;
        cp16(dst,      wb + bo0 * 32 + bs0 * 8);
        cp16(dst + 16, wb + bo0 * 32 + bs0 * 8 + 8);
        CP_COMMIT();
    };
    auto storeA = [&](int g) {
        int k = g >> 3;
        char* dA = dyn + (g & 1) * DBUF_B;
        int base = k * 512 + px;
        float w0 = s_pw[base], w1 = s_pw[base + 128], w2 = s_pw[base + 256], w3 = s_pw[base + 384];
        uint4 out;
        __half2* ho = (__half2*)&out;
#pragma unroll
        for (int q = 0; q < 4; q++) {
            float2 f0 = __half22float2(((const __half2*)&au[0])[q]);
            float2 f1 = __half22float2(((const __half2*)&au[1])[q]);
            float2 f2 = __half22float2(((const __half2*)&au[2])[q]);
            float2 f3 = __half22float2(((const __half2*)&au[3])[q]);
            float rx = fmaf(w3, f3.x, fmaf(w2, f2.x, fmaf(w1, f1.x, w0 * f0.x)));
            float ry = fmaf(w3, f3.y, fmaf(w2, f2.y, fmaf(w1, f1.y, w0 * f0.y)));
            ho[q] = __floats2half2_rn(rx, ry);
        }
        *(uint4*)(dA + px * (SAH * 2) + sg * 16) = out;
    };

    __syncthreads();          // pw/pi visible
    loadA(0);
    cpB(0);
    storeA(0);
    CP_WAIT0();
    __syncthreads();

    for (int g = 0; g < 72; g++) {
        if (g < 71) { loadA(g + 1); cpB(g + 1); }
        uint32_t bufByte = (uint32_t)(g & 1) * DBUF_B;
#pragma unroll
        for (int ks = 0; ks < 2; ks++) {
            uint32_t af[2][4];
#pragma unroll
            for (int mt = 0; mt < 2; mt++)
                ldsm4(af[mt][0], af[mt][1], af[mt][2], af[mt][3], aBase[mt] + bufByte + ks * 32);
#pragma unroll
            for (int j = 0; j < 4; j++) {
                uint32_t b0, b1, b2, b3;
                ldsm4(b0, b1, b2, b3, bBase[j] + bufByte + ks * 32);
                mma_f16(acc[0][2 * j], af[0], b0, b1);
                mma_f16(acc[1][2 * j], af[1], b0, b1);
                mma_f16(acc[0][2 * j + 1], af[0], b2, b3);
                mma_f16(acc[1][2 * j + 1], af[1], b2, b3);
            }
        }
        if (g < 71) storeA(g + 1);
        CP_WAIT0();
        __syncthreads();
    }

    // epilogue: store g_y NHWC + fused GN partial sums
    size_t rowbase = ((size_t)(b * HW) + y0 * 64);
#pragma unroll
    for (int mt = 0; mt < 2; mt++) {
        int p = wm * 32 + mt * 16 + (lane >> 2);
#pragma unroll
        for (int nt = 0; nt < 8; nt++) {
            int o = wn * 64 + nt * 8 + 2 * (lane & 3);
            float* d0 = g_y + (rowbase + p) * 256 + o;
            *(float2*)d0 = make_float2(acc[mt][nt][0], acc[mt][nt][1]);
            float* d1 = g_y + (rowbase + p + 8) * 256 + o;
            *(float2*)d1 = make_float2(acc[mt][nt][2], acc[mt][nt][3]);
        }
    }
#pragma unroll
    for (int nt = 0; nt < 8; nt++) {
        float s = 0.f, q = 0.f;
#pragma unroll
        for (int mt = 0; mt < 2; mt++)
#pragma unroll
            for (int i = 0; i < 4; i++) {
                float v = acc[mt][nt][i];
                s += v;
                q = fmaf(v, v, q);
            }
#pragma unroll
        for (int off = 16; off; off >>= 1) {
            s += __shfl_xor_sync(0xFFFFFFFFu, s, off);
            q += __shfl_xor_sync(0xFFFFFFFFu, q, off);
        }
        if (lane == 0) {
            int grp = wn * 8 + nt;
            atomicAdd(&g_gnsum[(b * 32 + grp) * 2], s);
            atomicAdd(&g_gnsum[(b * 32 + grp) * 2 + 1], q);
        }
    }
}

// ---------------- K3: GN stats ----------------
__global__ void k_gnstat() {
    int i = threadIdx.x;
    if (i < 128) {
        float S = g_gnsum[i * 2], Q = g_gnsum[i * 2 + 1];
        const float inv = 1.f / 32768.f;
        float m = S * inv;
        float var = Q * inv - m * m;
        g_gn[i * 2] = m;
        g_gn[i * 2 + 1] = rsqrtf(var + GEPS);
    }
}

// ---------------- K4: normalize + ReLU + NHWC->NCHW ----------------
__global__ void __launch_bounds__(1024) k_apply(const float* __restrict__ gamma,
                                                const float* __restrict__ beta,
                                                float* __restrict__ out) {
    __shared__ float sm[32][33];
    int b = blockIdx.z;
    int o0 = blockIdx.y << 5;
    int pt = blockIdx.x << 5;
    int tx = threadIdx.x & 31, ty = threadIdx.x >> 5;
    sm[ty][tx] = g_y[(((b * HW) + pt + ty) << 8) + o0 + tx];
    __syncthreads();
    int o = o0 + ty;
    float mean = g_gn[(b * 32 + (o >> 3)) * 2];
    float rstd = g_gn[(b * 32 + (o >> 3)) * 2 + 1];
    float v = sm[tx][ty];
    v = (v - mean) * rstd * gamma[o] + beta[o];
    out[((size_t)(b * OO + o) << 12) + pt + tx] = fmaxf(v, 0.f);
}

// ---------------- launch ----------------
extern "C" void kernel_launch(void* const* d_in, const int* in_sizes, int n_in,
                              void* d_out, int out_size) {
    const float* x        = (const float*)d_in[0];
    const float* offset_w = (const float*)d_in[1];
    const float* offset_b = (const float*)d_in[2];
    const float* deform_w = (const float*)d_in[3];
    const float* gn_gamma = (const float*)d_in[4];
    const float* gn_beta  = (const float*)d_in[5];
    float* out = (float*)d_out;

    cudaFuncSetAttribute(k_deform, cudaFuncAttributeMaxDynamicSharedMemorySize, DSMEM_TOT);

    k_xt<<<dim3(8, 64, 4), 256>>>(x);
    k_wt<<<(N_WDT + N_WOT + 256 + 255) / 256, 256>>>(deform_w, offset_w);
    k_offc<<<dim3(32, 4), 256>>>(offset_b);
    k_deform<<<dim3(32, 4), 512, DSMEM_TOT>>>();
    k_gnstat<<<1, 128>>>();
    k_apply<<<dim3(128, 8, 4), 1024>>>(gn_gamma, gn_beta, out);
}